// round 10
// baseline (speedup 1.0000x reference)
#include <cuda_runtime.h>

#define L_CHK 64                     // chunk length along T
#define SCRATCH_CAP_V4 (1 << 20)     // float4 count -> 16 MB each

// Pair-packed scratch: float4 = (re0, im0, re1, im1) for channels (2q, 2q+1).
// float2 view at [c*D + d] is layout-identical (used by scalar fallbacks).
__device__ float4 g_carry4 [SCRATCH_CAP_V4];
__device__ float4 g_prefix4[SCRATCH_CAP_V4];

// ===========================================================================
// Vector path (D % 4 == 0): 4 channels per thread, float4 traffic.
// ===========================================================================
__global__ void __launch_bounds__(128) dln_pass1_v4(
    const float* __restrict__ x,
    const float* __restrict__ sz,
    const float* __restrict__ th,
    int D, int T, int C)
{
    const int P4 = D >> 2;
    const int p  = blockIdx.x * blockDim.x + threadIdx.x;   // 4-channel group
    const int c  = blockIdx.y;
    if (p >= P4 || c >= C) return;

    const int t0  = c * L_CHK;
    const int len = (T - t0 < L_CHK) ? (T - t0) : L_CHK;

    const float4 s4 = ((const float4*)sz)[p];
    const float4 t4 = ((const float4*)th)[p];
    const float sa[4] = {s4.x, s4.y, s4.z, s4.w};
    const float ta[4] = {t4.x, t4.y, t4.z, t4.w};
    float zr[4], zi[4];
#pragma unroll
    for (int k = 0; k < 4; ++k) {
        const float r = expf(-expf(sa[k]));
        float si, co; sincosf(ta[k], &si, &co);
        zr[k] = r * co; zi[k] = r * si;
    }

    float vr[4] = {0.f, 0.f, 0.f, 0.f}, vi[4] = {0.f, 0.f, 0.f, 0.f};
    const float4* xp = (const float4*)(x + (long long)t0 * D) + p;

    if (len == L_CHK) {
#pragma unroll
        for (int t = 0; t < L_CHK; ++t) {
            const float4 xv = xp[t * P4];
            const float xa[4] = {xv.x, xv.y, xv.z, xv.w};
#pragma unroll
            for (int k = 0; k < 4; ++k) {
                const float nvr = fmaf(zr[k], vr[k], fmaf(-zi[k], vi[k], xa[k]));
                const float nvi = fmaf(zi[k], vr[k], zr[k] * vi[k]);
                vr[k] = nvr; vi[k] = nvi;
            }
        }
    } else {
        for (int t = 0; t < len; ++t) {
            const float4 xv = xp[t * P4];
            const float xa[4] = {xv.x, xv.y, xv.z, xv.w};
#pragma unroll
            for (int k = 0; k < 4; ++k) {
                const float nvr = fmaf(zr[k], vr[k], fmaf(-zi[k], vi[k], xa[k]));
                const float nvi = fmaf(zi[k], vr[k], zr[k] * vi[k]);
                vr[k] = nvr; vi[k] = nvi;
            }
        }
    }
    const long long base = (long long)c * (D >> 1) + 2 * p;
    g_carry4[base]     = make_float4(vr[0], vi[0], vr[1], vi[1]);
    g_carry4[base + 1] = make_float4(vr[2], vi[2], vr[3], vi[3]);
}

__global__ void __launch_bounds__(256) dln_pass2_v2(
    const float* __restrict__ sz,
    const float* __restrict__ th,
    int D, int C)
{
    const int P2 = D >> 1;
    const int q  = blockIdx.x * blockDim.x + threadIdx.x;   // channel pair
    if (q >= P2) return;

    const float2 s2 = ((const float2*)sz)[q];
    const float2 t2 = ((const float2*)th)[q];

    const float rL0 = expf(-(float)L_CHK * expf(s2.x));
    const float rL1 = expf(-(float)L_CHK * expf(s2.y));
    float si0, co0, si1, co1;
    sincosf((float)L_CHK * t2.x, &si0, &co0);
    sincosf((float)L_CHK * t2.y, &si1, &co1);
    const float zr0 = rL0 * co0, zi0 = rL0 * si0;
    const float zr1 = rL1 * co1, zi1 = rL1 * si1;

    float vr0 = 0.f, vi0 = 0.f, vr1 = 0.f, vi1 = 0.f;
    for (int c = 0; c < C; ++c) {
        const long long idx = (long long)c * P2 + q;
        g_prefix4[idx] = make_float4(vr0, vi0, vr1, vi1);
        const float4 cv = g_carry4[idx];
        float nvr = fmaf(zr0, vr0, fmaf(-zi0, vi0, cv.x));
        float nvi = fmaf(zi0, vr0, fmaf(zr0, vi0, cv.y));
        vr0 = nvr; vi0 = nvi;
        nvr = fmaf(zr1, vr1, fmaf(-zi1, vi1, cv.z));
        nvi = fmaf(zi1, vr1, fmaf(zr1, vi1, cv.w));
        vr1 = nvr; vi1 = nvi;
    }
}

__global__ void __launch_bounds__(128) dln_pass3_real_v4(
    const float* __restrict__ x,
    const float* __restrict__ sz,
    const float* __restrict__ th,
    float* __restrict__ out,
    int D, int T, int C, long long out_cap_floats)
{
    const int P4 = D >> 2;
    const int p  = blockIdx.x * blockDim.x + threadIdx.x;
    const int c  = blockIdx.y;
    if (p >= P4 || c >= C) return;

    const int t0  = c * L_CHK;
    const int len = (T - t0 < L_CHK) ? (T - t0) : L_CHK;

    const float4 s4 = ((const float4*)sz)[p];
    const float4 t4 = ((const float4*)th)[p];
    const float sa[4] = {s4.x, s4.y, s4.z, s4.w};
    const float ta[4] = {t4.x, t4.y, t4.z, t4.w};
    float zr[4], zi[4];
#pragma unroll
    for (int k = 0; k < 4; ++k) {
        const float r = expf(-expf(sa[k]));
        float si, co; sincosf(ta[k], &si, &co);
        zr[k] = r * co; zi[k] = r * si;
    }

    const long long base = (long long)c * (D >> 1) + 2 * p;
    const float4 a = g_prefix4[base];
    const float4 b = g_prefix4[base + 1];
    float vr[4] = {a.x, a.z, b.x, b.z};
    float vi[4] = {a.y, a.w, b.y, b.w};

    const float4* xp = (const float4*)(x + (long long)t0 * D) + p;

    if (len == L_CHK && (long long)(t0 + L_CHK) * D <= out_cap_floats) {
        float4* op = (float4*)(out + (long long)t0 * D) + p;
#pragma unroll
        for (int t = 0; t < L_CHK; ++t) {
            const float4 xv = xp[t * P4];
            const float xa[4] = {xv.x, xv.y, xv.z, xv.w};
#pragma unroll
            for (int k = 0; k < 4; ++k) {
                const float nvr = fmaf(zr[k], vr[k], fmaf(-zi[k], vi[k], xa[k]));
                const float nvi = fmaf(zi[k], vr[k], zr[k] * vi[k]);
                vr[k] = nvr; vi[k] = nvi;
            }
            __stcs(op + t * P4, make_float4(vr[0], vr[1], vr[2], vr[3]));
        }
    } else {
        for (int t = 0; t < len; ++t) {
            const float4 xv = xp[t * P4];
            const float xa[4] = {xv.x, xv.y, xv.z, xv.w};
#pragma unroll
            for (int k = 0; k < 4; ++k) {
                const float nvr = fmaf(zr[k], vr[k], fmaf(-zi[k], vi[k], xa[k]));
                const float nvi = fmaf(zi[k], vr[k], zr[k] * vi[k]);
                vr[k] = nvr; vi[k] = nvi;
            }
            const long long row = (long long)(t0 + t) * D + 4 * p;
#pragma unroll
            for (int k = 0; k < 4; ++k)
                if (row + k < out_cap_floats) __stcs(out + row + k, vr[k]);
        }
    }
}

// ===========================================================================
// Scalar fallbacks (any D) — share scratch via float2 view [c*D + d].
// ===========================================================================
__global__ void __launch_bounds__(256) dln_pass1_s(
    const float* __restrict__ x, const float* __restrict__ sz,
    const float* __restrict__ th, int D, int T, int C)
{
    float2* carry = (float2*)g_carry4;
    const int d = blockIdx.x * blockDim.x + threadIdx.x;
    const int c = blockIdx.y;
    if (d >= D || c >= C) return;
    const int t0  = c * L_CHK;
    const int len = (T - t0 < L_CHK) ? (T - t0) : L_CHK;
    const float r = expf(-expf(sz[d]));
    float si, co; sincosf(th[d], &si, &co);
    const float zr = r * co, zi = r * si;
    const float* xp = x + (long long)t0 * D + d;
    float vr = 0.f, vi = 0.f;
    for (int t = 0; t < len; ++t) {
        const float xv = xp[(long long)t * D];
        const float nvr = fmaf(zr, vr, fmaf(-zi, vi, xv));
        const float nvi = fmaf(zi, vr, zr * vi);
        vr = nvr; vi = nvi;
    }
    carry[(long long)c * D + d] = make_float2(vr, vi);
}

__global__ void __launch_bounds__(256) dln_pass2_s(
    const float* __restrict__ sz, const float* __restrict__ th, int D, int C)
{
    float2* carry  = (float2*)g_carry4;
    float2* prefix = (float2*)g_prefix4;
    const int d = blockIdx.x * blockDim.x + threadIdx.x;
    if (d >= D) return;
    const float rL = expf(-(float)L_CHK * expf(sz[d]));
    float si, co; sincosf((float)L_CHK * th[d], &si, &co);
    const float zLr = rL * co, zLi = rL * si;
    float vr = 0.f, vi = 0.f;
    for (int c = 0; c < C; ++c) {
        const long long idx = (long long)c * D + d;
        prefix[idx] = make_float2(vr, vi);
        const float2 cv = carry[idx];
        const float nvr = fmaf(zLr, vr, fmaf(-zLi, vi, cv.x));
        const float nvi = fmaf(zLi, vr, fmaf(zLr, vi, cv.y));
        vr = nvr; vi = nvi;
    }
}

__global__ void __launch_bounds__(256) dln_pass3_real_s(
    const float* __restrict__ x, const float* __restrict__ sz,
    const float* __restrict__ th, float* __restrict__ out,
    int D, int T, int C, long long out_cap_floats)
{
    float2* prefix = (float2*)g_prefix4;
    const int d = blockIdx.x * blockDim.x + threadIdx.x;
    const int c = blockIdx.y;
    if (d >= D || c >= C) return;
    const int t0  = c * L_CHK;
    const int len = (T - t0 < L_CHK) ? (T - t0) : L_CHK;
    const float r = expf(-expf(sz[d]));
    float si, co; sincosf(th[d], &si, &co);
    const float zr = r * co, zi = r * si;
    const float2 v0 = prefix[(long long)c * D + d];
    float vr = v0.x, vi = v0.y;
    const float* xp = x + (long long)t0 * D + d;
    for (int t = 0; t < len; ++t) {
        const float xv = xp[(long long)t * D];
        const float nvr = fmaf(zr, vr, fmaf(-zi, vi, xv));
        const float nvi = fmaf(zi, vr, zr * vi);
        vr = nvr; vi = nvi;
        const long long lidx = (long long)(t0 + t) * D + d;
        if (lidx < out_cap_floats) __stcs(out + lidx, vr);
    }
}

__global__ void __launch_bounds__(256) dln_pass3_cplx_s(
    const float* __restrict__ x, const float* __restrict__ sz,
    const float* __restrict__ th, float* __restrict__ out,
    int D, int T, int C, long long out_cap_floats)
{
    float2* prefix = (float2*)g_prefix4;
    const int d = blockIdx.x * blockDim.x + threadIdx.x;
    const int c = blockIdx.y;
    if (d >= D || c >= C) return;
    const int t0  = c * L_CHK;
    const int len = (T - t0 < L_CHK) ? (T - t0) : L_CHK;
    const float r = expf(-expf(sz[d]));
    float si, co; sincosf(th[d], &si, &co);
    const float zr = r * co, zi = r * si;
    const float2 v0 = prefix[(long long)c * D + d];
    float vr = v0.x, vi = v0.y;
    const float* xp = x + (long long)t0 * D + d;
    for (int t = 0; t < len; ++t) {
        const float xv = xp[(long long)t * D];
        const float nvr = fmaf(zr, vr, fmaf(-zi, vi, xv));
        const float nvi = fmaf(zi, vr, zr * vi);
        vr = nvr; vi = nvi;
        const long long o = 2 * ((long long)(t0 + t) * D + d);
        if (o + 1 < out_cap_floats) { __stcs(out + o, vr); __stcs(out + o + 1, vi); }
    }
}

extern "C" void kernel_launch(void* const* d_in, const int* in_sizes, int n_in,
                              void* d_out, int out_size)
{
    if (n_in < 3) return;

    int xi = 0;
    for (int i = 1; i < n_in; ++i)
        if (in_sizes[i] > in_sizes[xi]) xi = i;

    const float* x = (const float*)d_in[xi];
    const float* sv[2] = {nullptr, nullptr};
    long long    ss[2] = {0, 0};
    int ns = 0;
    for (int i = 0; i < n_in && ns < 2; ++i)
        if (i != xi) { sv[ns] = (const float*)d_in[i]; ss[ns] = in_sizes[i]; ++ns; }
    if (ns < 2) return;
    const float* sz = sv[0];
    const float* th = sv[1];

    const long long big   = in_sizes[xi];
    const long long small = ss[0] < ss[1] ? ss[0] : ss[1];
    if (small <= 0 || big <= 0 || big % small) return;

    const long long T = big / small;                 // unit-invariant
    if (T <= 0 || T > (1 << 20)) return;

    const long long osz = out_size;
    long long D = 0;
    int interleaved = 0;
    if (osz % T == 0 && (osz / T == small || 4 * (osz / T) == small)) {
        D = osz / T;  interleaved = 0;               // f32 real [T,D]
    } else if (osz % (2 * T) == 0 &&
               (osz / (2 * T) == small || 4 * (osz / (2 * T)) == small)) {
        D = osz / (2 * T);  interleaved = 1;         // interleaved complex
    } else return;
    if (D <= 0 || D > (1 << 20)) return;

    const int C = (int)((T + L_CHK - 1) / L_CHK);
    if ((long long)C * D > 2LL * SCRATCH_CAP_V4) return;  // float2 capacity

    if (!interleaved && (D & 3) == 0) {
        // Vector path
        const int P4 = (int)(D >> 2), P2 = (int)(D >> 1);
        dim3 blkA(128), blkB(256);
        dim3 g1((P4 + 127) / 128, (unsigned)C);
        dln_pass1_v4<<<g1, blkA>>>(x, sz, th, (int)D, (int)T, C);
        dln_pass2_v2<<<(P2 + 255) / 256, blkB>>>(sz, th, (int)D, C);
        dln_pass3_real_v4<<<g1, blkA>>>(x, sz, th, (float*)d_out,
                                        (int)D, (int)T, C, osz);
    } else {
        dim3 blk(256);
        dim3 gA((unsigned)((D + 255) / 256), (unsigned)C);
        dln_pass1_s<<<gA, blk>>>(x, sz, th, (int)D, (int)T, C);
        dln_pass2_s<<<(unsigned)((D + 255) / 256), blk>>>(sz, th, (int)D, C);
        if (interleaved)
            dln_pass3_cplx_s<<<gA, blk>>>(x, sz, th, (float*)d_out,
                                          (int)D, (int)T, C, osz);
        else
            dln_pass3_real_s<<<gA, blk>>>(x, sz, th, (float*)d_out,
                                          (int)D, (int)T, C, osz);
    }
}

// round 11
// speedup vs baseline: 1.8288x; 1.8288x over previous
#include <cuda_runtime.h>

#define L_CHK 32                     // chunk length along T
#define MAX_CPL 16                   // max chunks per lane in warp-scan pass2
#define SCRATCH_CAP_V4 (1 << 20)     // float4 count -> 16 MB each

// Scratch, pair-packed: float4 [c][q] = (re0,im0,re1,im1) for channels 2q,2q+1.
// float2 view at [c*D + d] is layout-identical (d = 2q + half).
__device__ float4 g_carry4 [SCRATCH_CAP_V4];
__device__ float4 g_prefix4[SCRATCH_CAP_V4];

// ===========================================================================
// Pass 1 (vector, D even): 2 channels/thread, float2 x loads.
// Grid ((D/2+255)/256, C), block 256 -> ~(D/2)*C threads.
// ===========================================================================
__global__ void __launch_bounds__(256) dln_pass1_v2(
    const float* __restrict__ x, const float* __restrict__ sz,
    const float* __restrict__ th, int D, int T, int C)
{
    const int P2 = D >> 1;
    const int q  = blockIdx.x * blockDim.x + threadIdx.x;
    const int c  = blockIdx.y;
    if (q >= P2 || c >= C) return;

    const int t0  = c * L_CHK;
    const int len = (T - t0 < L_CHK) ? (T - t0) : L_CHK;

    const float2 s2 = ((const float2*)sz)[q];
    const float2 t2 = ((const float2*)th)[q];
    const float r0 = expf(-expf(s2.x)), r1 = expf(-expf(s2.y));
    float si0, co0, si1, co1;
    sincosf(t2.x, &si0, &co0);
    sincosf(t2.y, &si1, &co1);
    const float zr0 = r0 * co0, zi0 = r0 * si0;
    const float zr1 = r1 * co1, zi1 = r1 * si1;

    const float2* xp = (const float2*)(x + (long long)t0 * D) + q;

    float vr0 = 0.f, vi0 = 0.f, vr1 = 0.f, vi1 = 0.f;
    if (len == L_CHK) {
#pragma unroll
        for (int t = 0; t < L_CHK; ++t) {
            const float2 xv = xp[t * P2];
            float nvr = fmaf(zr0, vr0, fmaf(-zi0, vi0, xv.x));
            float nvi = fmaf(zi0, vr0, zr0 * vi0);
            vr0 = nvr; vi0 = nvi;
            nvr = fmaf(zr1, vr1, fmaf(-zi1, vi1, xv.y));
            nvi = fmaf(zi1, vr1, zr1 * vi1);
            vr1 = nvr; vi1 = nvi;
        }
    } else {
        for (int t = 0; t < len; ++t) {
            const float2 xv = xp[t * P2];
            float nvr = fmaf(zr0, vr0, fmaf(-zi0, vi0, xv.x));
            float nvi = fmaf(zi0, vr0, zr0 * vi0);
            vr0 = nvr; vi0 = nvi;
            nvr = fmaf(zr1, vr1, fmaf(-zi1, vi1, xv.y));
            nvi = fmaf(zi1, vr1, zr1 * vi1);
            vr1 = nvr; vi1 = nvi;
        }
    }
    g_carry4[(long long)c * P2 + q] = make_float4(vr0, vi0, vr1, vi1);
}

// ===========================================================================
// Pass 2 (warp-per-channel Kogge-Stone scan over chunk carries).
// Element for chunk c: (p, w) = (z^L, carry_c); combine(a,b) = (pa*pb, va*pb+vb).
// Lane holds cpl consecutive chunks; local sweep -> warp shfl scan ->
// exclusive shift -> re-sweep writes exclusive prefixes.
// ===========================================================================
__global__ void __launch_bounds__(256) dln_pass2_w(
    const float* __restrict__ sz, const float* __restrict__ th,
    int D, int C, int cpl)
{
    const float2* carry2  = (const float2*)g_carry4;
    float2*       prefix2 = (float2*)g_prefix4;

    const int gtid = blockIdx.x * blockDim.x + threadIdx.x;
    const int d    = gtid >> 5;          // warp = channel
    const int lane = gtid & 31;
    if (d >= D) return;

    const float rL = expf(-(float)L_CHK * expf(sz[d]));   // |z|^L (0 on underflow)
    float si, co;
    sincosf((float)L_CHK * th[d], &si, &co);
    const float zr = rL * co, zi = rL * si;               // z^L

    // Load this lane's carries.
    float cr[MAX_CPL], ci[MAX_CPL];
#pragma unroll
    for (int i = 0; i < MAX_CPL; ++i) {
        if (i < cpl) {
            const int c = lane * cpl + i;
            if (c < C) {
                const float2 cv = carry2[(long long)c * D + d];
                cr[i] = cv.x; ci[i] = cv.y;
            } else { cr[i] = 0.f; ci[i] = 0.f; }
        }
    }

    // Local aggregate (P, V), identity (1, 0); invalid chunks = identity.
    float Pr = 1.f, Pi = 0.f, Vr = 0.f, Vi = 0.f;
#pragma unroll
    for (int i = 0; i < MAX_CPL; ++i) {
        if (i < cpl && lane * cpl + i < C) {
            const float nVr = fmaf(Vr, zr, fmaf(-Vi, zi, cr[i]));
            const float nVi = fmaf(Vr, zi, fmaf(Vi, zr, ci[i]));
            const float nPr = Pr * zr - Pi * zi;
            const float nPi = Pr * zi + Pi * zr;
            Vr = nVr; Vi = nVi; Pr = nPr; Pi = nPi;
        }
    }

    // Warp inclusive scan of lane aggregates.
#pragma unroll
    for (int k = 1; k < 32; k <<= 1) {
        const float aPr = __shfl_up_sync(0xffffffffu, Pr, k);
        const float aPi = __shfl_up_sync(0xffffffffu, Pi, k);
        const float aVr = __shfl_up_sync(0xffffffffu, Vr, k);
        const float aVi = __shfl_up_sync(0xffffffffu, Vi, k);
        if (lane >= k) {
            const float tVr = fmaf(aVr, Pr, fmaf(-aVi, Pi, Vr));
            const float tVi = fmaf(aVr, Pi, fmaf(aVi, Pr, Vi));
            const float tPr = aPr * Pr - aPi * Pi;
            const float tPi = aPr * Pi + aPi * Pr;
            Vr = tVr; Vi = tVi; Pr = tPr; Pi = tPi;
        }
    }

    // Exclusive: state before this lane's first chunk.
    float Rr = __shfl_up_sync(0xffffffffu, Vr, 1);
    float Ri = __shfl_up_sync(0xffffffffu, Vi, 1);
    if (lane == 0) { Rr = 0.f; Ri = 0.f; }

    // Re-sweep: emit exclusive prefix per chunk, then advance.
#pragma unroll
    for (int i = 0; i < MAX_CPL; ++i) {
        if (i < cpl) {
            const int c = lane * cpl + i;
            if (c < C) {
                prefix2[(long long)c * D + d] = make_float2(Rr, Ri);
                const float nRr = fmaf(Rr, zr, fmaf(-Ri, zi, cr[i]));
                const float nRi = fmaf(Rr, zi, fmaf(Ri, zr, ci[i]));
                Rr = nRr; Ri = nRi;
            }
        }
    }
}

// ===========================================================================
// Pass 3 (vector, REAL output mode): 2 channels/thread, float2 loads,
// float2 streaming stores of the real parts (channels adjacent).
// ===========================================================================
__global__ void __launch_bounds__(256) dln_pass3_real_v2(
    const float* __restrict__ x, const float* __restrict__ sz,
    const float* __restrict__ th, float* __restrict__ out,
    int D, int T, int C, long long out_cap_floats)
{
    const int P2 = D >> 1;
    const int q  = blockIdx.x * blockDim.x + threadIdx.x;
    const int c  = blockIdx.y;
    if (q >= P2 || c >= C) return;

    const int t0  = c * L_CHK;
    const int len = (T - t0 < L_CHK) ? (T - t0) : L_CHK;

    const float2 s2 = ((const float2*)sz)[q];
    const float2 t2 = ((const float2*)th)[q];
    const float r0 = expf(-expf(s2.x)), r1 = expf(-expf(s2.y));
    float si0, co0, si1, co1;
    sincosf(t2.x, &si0, &co0);
    sincosf(t2.y, &si1, &co1);
    const float zr0 = r0 * co0, zi0 = r0 * si0;
    const float zr1 = r1 * co1, zi1 = r1 * si1;

    const float4 v0 = g_prefix4[(long long)c * P2 + q];
    float vr0 = v0.x, vi0 = v0.y, vr1 = v0.z, vi1 = v0.w;

    const float2* xp = (const float2*)(x + (long long)t0 * D) + q;

    if (len == L_CHK && (long long)(t0 + L_CHK) * D <= out_cap_floats) {
        float2* op = (float2*)(out + (long long)t0 * D) + q;
#pragma unroll
        for (int t = 0; t < L_CHK; ++t) {
            const float2 xv = xp[t * P2];
            float nvr = fmaf(zr0, vr0, fmaf(-zi0, vi0, xv.x));
            float nvi = fmaf(zi0, vr0, zr0 * vi0);
            vr0 = nvr; vi0 = nvi;
            nvr = fmaf(zr1, vr1, fmaf(-zi1, vi1, xv.y));
            nvi = fmaf(zi1, vr1, zr1 * vi1);
            vr1 = nvr; vi1 = nvi;
            __stcs(op + t * P2, make_float2(vr0, vr1));
        }
    } else {
        for (int t = 0; t < len; ++t) {
            const float2 xv = xp[t * P2];
            float nvr = fmaf(zr0, vr0, fmaf(-zi0, vi0, xv.x));
            float nvi = fmaf(zi0, vr0, zr0 * vi0);
            vr0 = nvr; vi0 = nvi;
            nvr = fmaf(zr1, vr1, fmaf(-zi1, vi1, xv.y));
            nvi = fmaf(zi1, vr1, zr1 * vi1);
            vr1 = nvr; vi1 = nvi;
            const long long row = (long long)(t0 + t) * D + 2 * q;
            if (row     < out_cap_floats) __stcs(out + row,     vr0);
            if (row + 1 < out_cap_floats) __stcs(out + row + 1, vr1);
        }
    }
}

// ===========================================================================
// Scalar fallbacks (any D / interleaved mode) — float2 scratch view [c*D+d].
// ===========================================================================
__global__ void __launch_bounds__(256) dln_pass1_s(
    const float* __restrict__ x, const float* __restrict__ sz,
    const float* __restrict__ th, int D, int T, int C)
{
    float2* carry = (float2*)g_carry4;
    const int d = blockIdx.x * blockDim.x + threadIdx.x;
    const int c = blockIdx.y;
    if (d >= D || c >= C) return;
    const int t0  = c * L_CHK;
    const int len = (T - t0 < L_CHK) ? (T - t0) : L_CHK;
    const float r = expf(-expf(sz[d]));
    float si, co; sincosf(th[d], &si, &co);
    const float zr = r * co, zi = r * si;
    const float* xp = x + (long long)t0 * D + d;
    float vr = 0.f, vi = 0.f;
    for (int t = 0; t < len; ++t) {
        const float xv = xp[(long long)t * D];
        const float nvr = fmaf(zr, vr, fmaf(-zi, vi, xv));
        const float nvi = fmaf(zi, vr, zr * vi);
        vr = nvr; vi = nvi;
    }
    carry[(long long)c * D + d] = make_float2(vr, vi);
}

__global__ void __launch_bounds__(256) dln_pass2_s(
    const float* __restrict__ sz, const float* __restrict__ th, int D, int C)
{
    float2* carry  = (float2*)g_carry4;
    float2* prefix = (float2*)g_prefix4;
    const int d = blockIdx.x * blockDim.x + threadIdx.x;
    if (d >= D) return;
    const float rL = expf(-(float)L_CHK * expf(sz[d]));
    float si, co; sincosf((float)L_CHK * th[d], &si, &co);
    const float zLr = rL * co, zLi = rL * si;
    float vr = 0.f, vi = 0.f;
    for (int c = 0; c < C; ++c) {
        const long long idx = (long long)c * D + d;
        prefix[idx] = make_float2(vr, vi);
        const float2 cv = carry[idx];
        const float nvr = fmaf(zLr, vr, fmaf(-zLi, vi, cv.x));
        const float nvi = fmaf(zLi, vr, fmaf(zLr, vi, cv.y));
        vr = nvr; vi = nvi;
    }
}

__global__ void __launch_bounds__(256) dln_pass3_real_s(
    const float* __restrict__ x, const float* __restrict__ sz,
    const float* __restrict__ th, float* __restrict__ out,
    int D, int T, int C, long long out_cap_floats)
{
    float2* prefix = (float2*)g_prefix4;
    const int d = blockIdx.x * blockDim.x + threadIdx.x;
    const int c = blockIdx.y;
    if (d >= D || c >= C) return;
    const int t0  = c * L_CHK;
    const int len = (T - t0 < L_CHK) ? (T - t0) : L_CHK;
    const float r = expf(-expf(sz[d]));
    float si, co; sincosf(th[d], &si, &co);
    const float zr = r * co, zi = r * si;
    const float2 v0 = prefix[(long long)c * D + d];
    float vr = v0.x, vi = v0.y;
    const float* xp = x + (long long)t0 * D + d;
    for (int t = 0; t < len; ++t) {
        const float xv = xp[(long long)t * D];
        const float nvr = fmaf(zr, vr, fmaf(-zi, vi, xv));
        const float nvi = fmaf(zi, vr, zr * vi);
        vr = nvr; vi = nvi;
        const long long lidx = (long long)(t0 + t) * D + d;
        if (lidx < out_cap_floats) __stcs(out + lidx, vr);
    }
}

__global__ void __launch_bounds__(256) dln_pass3_cplx_s(
    const float* __restrict__ x, const float* __restrict__ sz,
    const float* __restrict__ th, float* __restrict__ out,
    int D, int T, int C, long long out_cap_floats)
{
    float2* prefix = (float2*)g_prefix4;
    const int d = blockIdx.x * blockDim.x + threadIdx.x;
    const int c = blockIdx.y;
    if (d >= D || c >= C) return;
    const int t0  = c * L_CHK;
    const int len = (T - t0 < L_CHK) ? (T - t0) : L_CHK;
    const float r = expf(-expf(sz[d]));
    float si, co; sincosf(th[d], &si, &co);
    const float zr = r * co, zi = r * si;
    const float2 v0 = prefix[(long long)c * D + d];
    float vr = v0.x, vi = v0.y;
    const float* xp = x + (long long)t0 * D + d;
    for (int t = 0; t < len; ++t) {
        const float xv = xp[(long long)t * D];
        const float nvr = fmaf(zr, vr, fmaf(-zi, vi, xv));
        const float nvi = fmaf(zi, vr, zr * vi);
        vr = nvr; vi = nvi;
        const long long o = 2 * ((long long)(t0 + t) * D + d);
        if (o + 1 < out_cap_floats) { __stcs(out + o, vr); __stcs(out + o + 1, vi); }
    }
}

extern "C" void kernel_launch(void* const* d_in, const int* in_sizes, int n_in,
                              void* d_out, int out_size)
{
    if (n_in < 3) return;

    int xi = 0;
    for (int i = 1; i < n_in; ++i)
        if (in_sizes[i] > in_sizes[xi]) xi = i;

    const float* x = (const float*)d_in[xi];
    const float* sv[2] = {nullptr, nullptr};
    long long    ss[2] = {0, 0};
    int ns = 0;
    for (int i = 0; i < n_in && ns < 2; ++i)
        if (i != xi) { sv[ns] = (const float*)d_in[i]; ss[ns] = in_sizes[i]; ++ns; }
    if (ns < 2) return;
    const float* sz = sv[0];
    const float* th = sv[1];

    const long long big   = in_sizes[xi];
    const long long small = ss[0] < ss[1] ? ss[0] : ss[1];
    if (small <= 0 || big <= 0 || big % small) return;

    const long long T = big / small;                 // unit-invariant
    if (T <= 0 || T > (1 << 20)) return;

    const long long osz = out_size;
    long long D = 0;
    int interleaved = 0;
    if (osz % T == 0 && (osz / T == small || 4 * (osz / T) == small)) {
        D = osz / T;  interleaved = 0;               // f32 real [T,D]
    } else if (osz % (2 * T) == 0 &&
               (osz / (2 * T) == small || 4 * (osz / (2 * T)) == small)) {
        D = osz / (2 * T);  interleaved = 1;         // interleaved complex
    } else return;
    if (D <= 0 || D > (1 << 20)) return;

    const int C   = (int)((T + L_CHK - 1) / L_CHK);
    const int cpl = (C + 31) / 32;
    if ((long long)C * D > 2LL * SCRATCH_CAP_V4) return;   // float2 capacity

    dim3 blk(256);
    if (!interleaved && (D & 1) == 0 && cpl <= MAX_CPL) {
        const int P2 = (int)(D >> 1);
        dim3 g1((P2 + 255) / 256, (unsigned)C);
        dln_pass1_v2<<<g1, blk>>>(x, sz, th, (int)D, (int)T, C);
        dln_pass2_w<<<(unsigned)(((long long)D * 32 + 255) / 256), blk>>>(
            sz, th, (int)D, C, cpl);
        dln_pass3_real_v2<<<g1, blk>>>(x, sz, th, (float*)d_out,
                                       (int)D, (int)T, C, osz);
    } else {
        dim3 gA((unsigned)((D + 255) / 256), (unsigned)C);
        dln_pass1_s<<<gA, blk>>>(x, sz, th, (int)D, (int)T, C);
        if (cpl <= MAX_CPL)
            dln_pass2_w<<<(unsigned)(((long long)D * 32 + 255) / 256), blk>>>(
                sz, th, (int)D, C, cpl);
        else
            dln_pass2_s<<<(unsigned)((D + 255) / 256), blk>>>(sz, th, (int)D, C);
        if (interleaved)
            dln_pass3_cplx_s<<<gA, blk>>>(x, sz, th, (float*)d_out,
                                          (int)D, (int)T, C, osz);
        else
            dln_pass3_real_s<<<gA, blk>>>(x, sz, th, (float*)d_out,
                                          (int)D, (int)T, C, osz);
    }
}